// round 7
// baseline (speedup 1.0000x reference)
#include <cuda_runtime.h>

#define B_   32
#define S_   1024
#define ATT_ 512
#define W_   8

// ---------------- scratch (no allocations allowed) ----------------
__device__ float g_qbm[B_ * ATT_];   // dec_h @ Wm^T + bm
__device__ float g_qbc[B_ * ATT_];   // dec_h @ Wc^T + bc
__device__ float g_vnm[ATT_];        // gm * vm / ||vm||
__device__ float g_vnc[ATT_];
__device__ float g_me[B_ * S_];      // monotonic energy
__device__ float g_ce[B_ * S_];      // chunk energy
__device__ float g_beta[B_ * S_];

__device__ __forceinline__ float tanha(float x) {
    float y;
    asm("tanh.approx.f32 %0, %1;" : "=f"(y) : "f"(x));
    return y;
}

// ---------------- K0: matvec + vnorm + zero (fused pre-pass) ------
__global__ void __launch_bounds__(256) k_pre(
        const float* __restrict__ dec,
        const float* __restrict__ Wm, const float* __restrict__ bm,
        const float* __restrict__ Wc, const float* __restrict__ bc,
        const float* __restrict__ vm, const float* __restrict__ gm,
        const float* __restrict__ vc, const float* __restrict__ gc,
        float* __restrict__ out) {
    int t = threadIdx.x;

    if (blockIdx.y == 2) {
        int x = blockIdx.x;
        out[x * 512 + t] = 0.f;
        out[x * 512 + 256 + t] = 0.f;
        if (x > 1) return;
        const float* v = x ? vc : vm;
        const float* g = x ? gc : gm;
        float* o       = x ? g_vnc : g_vnm;
        float x1 = v[t], x2 = v[t + 256];
        float ss = x1 * x1 + x2 * x2;
        __shared__ float red[8];
        #pragma unroll
        for (int off = 16; off; off >>= 1) ss += __shfl_down_sync(0xffffffffu, ss, off);
        if ((t & 31) == 0) red[t >> 5] = ss;
        __syncthreads();
        __shared__ float s_scale;
        if (t == 0) {
            float a = red[0] + red[1] + red[2] + red[3] + red[4] + red[5] + red[6] + red[7];
            s_scale = __ldg(g) / sqrtf(a);
        }
        __syncthreads();
        o[t] = x1 * s_scale;
        o[t + 256] = x2 * s_scale;
        return;
    }

    const float* W    = blockIdx.y ? Wc : Wm;
    const float* bias = blockIdx.y ? bc : bm;
    float* qout       = blockIdx.y ? g_qbc : g_qbm;

    int w = t >> 5, lane = t & 31;
    int row0 = blockIdx.x * 16 + w * 2;          // 2 rows per warp

    const float4* W40 = reinterpret_cast<const float4*>(W + (size_t)row0 * 512);
    const float4* W41 = reinterpret_cast<const float4*>(W + (size_t)(row0 + 1) * 512);
    float4 w0[4], w1[4];
    #pragma unroll
    for (int j = 0; j < 4; j++) { w0[j] = W40[lane + 32 * j]; w1[j] = W41[lane + 32 * j]; }
    float bias0 = bias[row0], bias1 = bias[row0 + 1];

    __shared__ float4 sdec[16 * 128];            // 32 KB: 16 batches
    const float4* dec4 = reinterpret_cast<const float4*>(dec);

    #pragma unroll
    for (int half = 0; half < 2; half++) {
        #pragma unroll
        for (int i = t; i < 2048; i += 256) sdec[i] = dec4[half * 2048 + i];
        __syncthreads();
        #pragma unroll 4
        for (int bb = 0; bb < 16; bb++) {
            int b = half * 16 + bb;
            float a0 = 0.f, a1 = 0.f;
            #pragma unroll
            for (int j = 0; j < 4; j++) {
                float4 dv = sdec[bb * 128 + lane + 32 * j];
                a0 += w0[j].x * dv.x + w0[j].y * dv.y + w0[j].z * dv.z + w0[j].w * dv.w;
                a1 += w1[j].x * dv.x + w1[j].y * dv.y + w1[j].z * dv.z + w1[j].w * dv.w;
            }
            #pragma unroll
            for (int off = 16; off; off >>= 1) {
                a0 += __shfl_down_sync(0xffffffffu, a0, off);
                a1 += __shfl_down_sync(0xffffffffu, a1, off);
            }
            if (lane == 0) {
                qout[b * ATT_ + row0]     = a0 + bias0;
                qout[b * ATT_ + row0 + 1] = a1 + bias1;
            }
        }
        __syncthreads();
    }
}

// ---------------- K1: fused energies over key + value L2 prefetch --
// While streaming key (latency-bound, ~57% DRAM), pull the matching
// value slice into L2 with evict_last priority using the spare bus.
__global__ void __launch_bounds__(256) k_energy(
        const float* __restrict__ key, const float* __restrict__ value,
        const float* __restrict__ vbm, const float* __restrict__ rm,
        const float* __restrict__ vbc, const float* __restrict__ rc) {
    int b = blockIdx.y, tile = blockIdx.x;
    int t = threadIdx.x, w = t >> 5, lane = t & 31;

    // fire-and-forget: prefetch this (b, tile) value slice (64 KB = 512 lines)
    {
        const float* vslice = value + (((size_t)b * S_ + tile * 32) << 9);
        asm volatile("prefetch.global.L2::evict_last [%0];" :: "l"(vslice + (size_t)t * 32));
        asm volatile("prefetch.global.L2::evict_last [%0];" :: "l"(vslice + (size_t)(t + 256) * 32));
    }

    __shared__ float sq[2048];   // [qm 512 | qc 512 | vm 512 | vc 512]
    {
        const float4* qm4 = reinterpret_cast<const float4*>(g_qbm + b * ATT_);
        const float4* qc4 = reinterpret_cast<const float4*>(g_qbc + b * ATT_);
        const float4* vm4 = reinterpret_cast<const float4*>(g_vnm);
        const float4* vc4 = reinterpret_cast<const float4*>(g_vnc);
        float4* s4 = reinterpret_cast<float4*>(sq);
        if (t < 128) {
            s4[t]       = qm4[t];
            s4[256 + t] = vm4[t];
        } else {
            int u = t - 128;
            s4[128 + u] = qc4[u];
            s4[384 + u] = vc4[u];
        }
    }
    __syncthreads();

    float qm[16], qc[16], vmr[16], vcr[16];
    #pragma unroll
    for (int j = 0; j < 16; j++) {
        qm[j]  = sq[lane + 32 * j];
        qc[j]  = sq[512 + lane + 32 * j];
        vmr[j] = sq[1024 + lane + 32 * j];
        vcr[j] = sq[1536 + lane + 32 * j];
    }
    const float cm = __ldg(vbm) + __ldg(rm);
    const float cc = __ldg(vbc) + __ldg(rc);

    int s0 = tile * 32 + w * 4;
    #pragma unroll
    for (int r = 0; r < 4; r++) {
        int s = s0 + r;
        const float* kp = key + (((size_t)b * S_ + s) << 9);
        float kv[16];
        #pragma unroll
        for (int j = 0; j < 16; j++) kv[j] = kp[lane + 32 * j];
        float em = 0.f, ec = 0.f;
        #pragma unroll
        for (int j = 0; j < 16; j++) {
            em += vmr[j] * tanha(qm[j] + kv[j]);
            ec += vcr[j] * tanha(qc[j] + kv[j]);
        }
        #pragma unroll
        for (int off = 16; off; off >>= 1) {
            em += __shfl_down_sync(0xffffffffu, em, off);
            ec += __shfl_down_sync(0xffffffffu, ec, off);
        }
        if (lane == 0) {
            g_me[b * S_ + s] = em + cm;
            g_ce[b * S_ + s] = ec + cc;
        }
    }
}

// ---------------- K2: per-batch scans + windows -> beta -----------
__global__ void __launch_bounds__(1024) k_scan(const float* __restrict__ noise,
                                               const float* __restrict__ prev) {
    int b = blockIdx.x, s = threadIdx.x;   // 1024 threads
    int lane = s & 31, wid = s >> 5;
    const int base = b * S_;
    __shared__ float smA[S_];
    __shared__ float smC[S_];
    __shared__ float wa[32], wb[32], wc[32];
    __shared__ float s_psum;

    float e  = g_me[base + s];
    float nz = noise[base + s];
    float pv = prev[base + s];
    float c  = g_ce[base + s];
    smC[s] = c;

    float p = 1.f / (1.f + __expf(-(e + nz)));
    if (s == S_ - 1) p = 1.f;
    float omp = 1.f - p;

    float x = omp;
    #pragma unroll
    for (int o = 1; o < 32; o <<= 1) {
        float y = __shfl_up_sync(0xffffffffu, x, o);
        if (lane >= o) x *= y;
    }
    if (lane == 31) wa[wid] = x;
    float ts = pv;
    #pragma unroll
    for (int off = 16; off; off >>= 1) ts += __shfl_down_sync(0xffffffffu, ts, off);
    if (lane == 0) wb[wid] = ts;
    __syncthreads();                                        // B1

    if (wid == 0) {
        float a = wa[lane];
        #pragma unroll
        for (int o = 1; o < 32; o <<= 1) {
            float y = __shfl_up_sync(0xffffffffu, a, o);
            if (lane >= o) a *= y;
        }
        wa[lane] = a;
    } else if (wid == 1) {
        float a = wb[lane];
        #pragma unroll
        for (int off = 16; off; off >>= 1) a += __shfl_down_sync(0xffffffffu, a, off);
        if (lane == 0) s_psum = a;
    }
    __syncthreads();                                        // B2

    float ip = wid ? x * wa[wid - 1] : x;
    smA[s] = ip;
    __syncthreads();                                        // B3

    float cp = s ? smA[s - 1] : 1.f;
    float cpc = fminf(fmaxf(cp, 1e-20f), 1.f);
    float y2 = (pv / s_psum) / cpc;

    float xs = y2;
    #pragma unroll
    for (int o = 1; o < 32; o <<= 1) {
        float y = __shfl_up_sync(0xffffffffu, xs, o);
        if (lane >= o) xs += y;
    }
    if (lane == 31) wc[wid] = xs;
    __syncthreads();                                        // B4
    if (wid == 0) {
        float a = wc[lane];
        #pragma unroll
        for (int o = 1; o < 32; o <<= 1) {
            float y = __shfl_up_sync(0xffffffffu, a, o);
            if (lane >= o) a += y;
        }
        wc[lane] = a;
    }
    __syncthreads();                                        // B5
    float cs = wid ? xs + wc[wid - 1] : xs;
    float alpha = p * cp * cs;

    float mx = c;
    #pragma unroll
    for (int j = 1; j < W_; j++) { int i = s - j; if (i >= 0) mx = fmaxf(mx, smC[i]); }
    float eu = __expf(c - mx);
    smA[s] = eu;
    __syncthreads();                                        // B6

    float den = 0.f;
    #pragma unroll
    for (int j = 0; j < W_; j++) { int i = s - j; if (i >= 0) den += smA[i]; }
    den = fmaxf(den, 1e-10f);
    float g = alpha / den;
    smC[s] = g;
    __syncthreads();                                        // B7

    float acc = 0.f;
    #pragma unroll
    for (int j = 0; j < W_; j++) { int i = s + j; if (i < S_) acc += smC[i]; }
    g_beta[base + s] = eu * acc;
}

// ---------------- K3: context = beta . value (L2-hit stream) ------
#define SCHUNK_ 32
__global__ void __launch_bounds__(256) k_ctx(const float* __restrict__ value,
                                             float* __restrict__ out) {
    int b = blockIdx.y, sc = blockIdx.x;     // 32 chunks of 32 rows
    int t = threadIdx.x;
    __shared__ float sb[SCHUNK_];
    if (t < SCHUNK_) sb[t] = g_beta[b * S_ + sc * SCHUNK_ + t];
    __syncthreads();
    const float* vp = value + (((size_t)b * S_ + sc * SCHUNK_) << 9);
    float a0 = 0.f, a1 = 0.f;
    #pragma unroll
    for (int s = 0; s < SCHUNK_; s++) {
        float bs = sb[s];
        a0 += bs * vp[(s << 9) + t];
        a1 += bs * vp[(s << 9) + t + 256];
    }
    atomicAdd(out + b * 512 + t,       a0);
    atomicAdd(out + b * 512 + t + 256, a1);
}

// ---------------- launch ------------------------------------------
extern "C" void kernel_launch(void* const* d_in, const int* in_sizes, int n_in,
                              void* d_out, int out_size) {
    const float* dec   = (const float*)d_in[0];
    const float* key   = (const float*)d_in[1];
    const float* value = (const float*)d_in[2];
    const float* prev  = (const float*)d_in[3];
    const float* noise = (const float*)d_in[4];
    const float* Wm    = (const float*)d_in[5];
    const float* bm    = (const float*)d_in[6];
    const float* vm    = (const float*)d_in[7];
    const float* gm    = (const float*)d_in[8];
    const float* vbm   = (const float*)d_in[9];
    const float* rm    = (const float*)d_in[10];
    const float* Wc    = (const float*)d_in[11];
    const float* bc    = (const float*)d_in[12];
    const float* vc    = (const float*)d_in[13];
    const float* gc    = (const float*)d_in[14];
    const float* vbc   = (const float*)d_in[15];
    const float* rc    = (const float*)d_in[16];
    float* out = (float*)d_out;

    k_pre<<<dim3(32, 3), 256>>>(dec, Wm, bm, Wc, bc, vm, gm, vc, gc, out);
    k_energy<<<dim3(S_ / 32, B_), 256>>>(key, value, vbm, rm, vbc, rc);
    k_scan<<<B_, S_>>>(noise, prev);
    k_ctx<<<dim3(S_ / SCHUNK_, B_), 256>>>(value, out);
}

// round 8
// speedup vs baseline: 1.3066x; 1.3066x over previous
#include <cuda_runtime.h>

#define B_   32
#define S_   1024
#define ATT_ 512
#define W_   8

// ---------------- scratch (no allocations allowed) ----------------
__device__ float g_qbm[B_ * ATT_];   // dec_h @ Wm^T + bm
__device__ float g_qbc[B_ * ATT_];   // dec_h @ Wc^T + bc
__device__ float g_vnm[ATT_];        // gm * vm / ||vm||
__device__ float g_vnc[ATT_];
__device__ float g_me[B_ * S_];      // monotonic energy
__device__ float g_ce[B_ * S_];      // chunk energy
__device__ float g_beta[B_ * S_];

__device__ __forceinline__ float tanha(float x) {
    float y;
    asm("tanh.approx.f32 %0, %1;" : "=f"(y) : "f"(x));
    return y;
}

// ---------------- K0: matvec + vnorm + zero (fused pre-pass) ------
__global__ void __launch_bounds__(256) k_pre(
        const float* __restrict__ dec,
        const float* __restrict__ Wm, const float* __restrict__ bm,
        const float* __restrict__ Wc, const float* __restrict__ bc,
        const float* __restrict__ vm, const float* __restrict__ gm,
        const float* __restrict__ vc, const float* __restrict__ gc,
        float* __restrict__ out) {
    int t = threadIdx.x;

    if (blockIdx.y == 2) {
        int x = blockIdx.x;
        out[x * 512 + t] = 0.f;
        out[x * 512 + 256 + t] = 0.f;
        if (x > 1) return;
        const float* v = x ? vc : vm;
        const float* g = x ? gc : gm;
        float* o       = x ? g_vnc : g_vnm;
        float x1 = v[t], x2 = v[t + 256];
        float ss = x1 * x1 + x2 * x2;
        __shared__ float red[8];
        #pragma unroll
        for (int off = 16; off; off >>= 1) ss += __shfl_down_sync(0xffffffffu, ss, off);
        if ((t & 31) == 0) red[t >> 5] = ss;
        __syncthreads();
        __shared__ float s_scale;
        if (t == 0) {
            float a = red[0] + red[1] + red[2] + red[3] + red[4] + red[5] + red[6] + red[7];
            s_scale = __ldg(g) / sqrtf(a);
        }
        __syncthreads();
        o[t] = x1 * s_scale;
        o[t + 256] = x2 * s_scale;
        return;
    }

    const float* W    = blockIdx.y ? Wc : Wm;
    const float* bias = blockIdx.y ? bc : bm;
    float* qout       = blockIdx.y ? g_qbc : g_qbm;

    int w = t >> 5, lane = t & 31;
    int row0 = blockIdx.x * 16 + w * 2;          // 2 rows per warp

    const float4* W40 = reinterpret_cast<const float4*>(W + (size_t)row0 * 512);
    const float4* W41 = reinterpret_cast<const float4*>(W + (size_t)(row0 + 1) * 512);
    float4 w0[4], w1[4];
    #pragma unroll
    for (int j = 0; j < 4; j++) { w0[j] = W40[lane + 32 * j]; w1[j] = W41[lane + 32 * j]; }
    float bias0 = bias[row0], bias1 = bias[row0 + 1];

    __shared__ float4 sdec[16 * 128];            // 32 KB: 16 batches
    const float4* dec4 = reinterpret_cast<const float4*>(dec);

    #pragma unroll
    for (int half = 0; half < 2; half++) {
        #pragma unroll
        for (int i = t; i < 2048; i += 256) sdec[i] = dec4[half * 2048 + i];
        __syncthreads();
        #pragma unroll 4
        for (int bb = 0; bb < 16; bb++) {
            int b = half * 16 + bb;
            float a0 = 0.f, a1 = 0.f;
            #pragma unroll
            for (int j = 0; j < 4; j++) {
                float4 dv = sdec[bb * 128 + lane + 32 * j];
                a0 += w0[j].x * dv.x + w0[j].y * dv.y + w0[j].z * dv.z + w0[j].w * dv.w;
                a1 += w1[j].x * dv.x + w1[j].y * dv.y + w1[j].z * dv.z + w1[j].w * dv.w;
            }
            #pragma unroll
            for (int off = 16; off; off >>= 1) {
                a0 += __shfl_down_sync(0xffffffffu, a0, off);
                a1 += __shfl_down_sync(0xffffffffu, a1, off);
            }
            if (lane == 0) {
                qout[b * ATT_ + row0]     = a0 + bias0;
                qout[b * ATT_ + row0 + 1] = a1 + bias1;
            }
        }
        __syncthreads();
    }
}

// ---------------- K1: fused energies over key ---------------------
__global__ void __launch_bounds__(256) k_energy(
        const float* __restrict__ key,
        const float* __restrict__ vbm, const float* __restrict__ rm,
        const float* __restrict__ vbc, const float* __restrict__ rc) {
    int b = blockIdx.y, tile = blockIdx.x;
    int t = threadIdx.x, w = t >> 5, lane = t & 31;

    __shared__ float sq[2048];   // [qm 512 | qc 512 | vm 512 | vc 512]
    {
        const float4* qm4 = reinterpret_cast<const float4*>(g_qbm + b * ATT_);
        const float4* qc4 = reinterpret_cast<const float4*>(g_qbc + b * ATT_);
        const float4* vm4 = reinterpret_cast<const float4*>(g_vnm);
        const float4* vc4 = reinterpret_cast<const float4*>(g_vnc);
        float4* s4 = reinterpret_cast<float4*>(sq);
        if (t < 128) {
            s4[t]       = qm4[t];
            s4[256 + t] = vm4[t];
        } else {
            int u = t - 128;
            s4[128 + u] = qc4[u];
            s4[384 + u] = vc4[u];
        }
    }
    __syncthreads();

    float qm[16], qc[16], vmr[16], vcr[16];
    #pragma unroll
    for (int j = 0; j < 16; j++) {
        qm[j]  = sq[lane + 32 * j];
        qc[j]  = sq[512 + lane + 32 * j];
        vmr[j] = sq[1024 + lane + 32 * j];
        vcr[j] = sq[1536 + lane + 32 * j];
    }
    const float cm = __ldg(vbm) + __ldg(rm);
    const float cc = __ldg(vbc) + __ldg(rc);

    int s0 = tile * 32 + w * 4;
    #pragma unroll
    for (int r = 0; r < 4; r++) {
        int s = s0 + r;
        const float* kp = key + (((size_t)b * S_ + s) << 9);
        float kv[16];
        #pragma unroll
        for (int j = 0; j < 16; j++) kv[j] = kp[lane + 32 * j];
        float em = 0.f, ec = 0.f;
        #pragma unroll
        for (int j = 0; j < 16; j++) {
            em += vmr[j] * tanha(qm[j] + kv[j]);
            ec += vcr[j] * tanha(qc[j] + kv[j]);
        }
        #pragma unroll
        for (int off = 16; off; off >>= 1) {
            em += __shfl_down_sync(0xffffffffu, em, off);
            ec += __shfl_down_sync(0xffffffffu, ec, off);
        }
        if (lane == 0) {
            g_me[b * S_ + s] = em + cm;
            g_ce[b * S_ + s] = ec + cc;
        }
    }
}

// ---------------- K2: per-batch scans + windows -> beta -----------
__global__ void __launch_bounds__(1024) k_scan(const float* __restrict__ noise,
                                               const float* __restrict__ prev) {
    int b = blockIdx.x, s = threadIdx.x;   // 1024 threads
    int lane = s & 31, wid = s >> 5;
    const int base = b * S_;
    __shared__ float smA[S_];
    __shared__ float smC[S_];
    __shared__ float wa[32], wb[32], wc[32];
    __shared__ float s_psum;

    float e  = g_me[base + s];
    float nz = noise[base + s];
    float pv = prev[base + s];
    float c  = g_ce[base + s];
    smC[s] = c;

    float p = 1.f / (1.f + __expf(-(e + nz)));
    if (s == S_ - 1) p = 1.f;
    float omp = 1.f - p;

    float x = omp;
    #pragma unroll
    for (int o = 1; o < 32; o <<= 1) {
        float y = __shfl_up_sync(0xffffffffu, x, o);
        if (lane >= o) x *= y;
    }
    if (lane == 31) wa[wid] = x;
    float ts = pv;
    #pragma unroll
    for (int off = 16; off; off >>= 1) ts += __shfl_down_sync(0xffffffffu, ts, off);
    if (lane == 0) wb[wid] = ts;
    __syncthreads();                                        // B1

    if (wid == 0) {
        float a = wa[lane];
        #pragma unroll
        for (int o = 1; o < 32; o <<= 1) {
            float y = __shfl_up_sync(0xffffffffu, a, o);
            if (lane >= o) a *= y;
        }
        wa[lane] = a;
    } else if (wid == 1) {
        float a = wb[lane];
        #pragma unroll
        for (int off = 16; off; off >>= 1) a += __shfl_down_sync(0xffffffffu, a, off);
        if (lane == 0) s_psum = a;
    }
    __syncthreads();                                        // B2

    float ip = wid ? x * wa[wid - 1] : x;
    smA[s] = ip;
    __syncthreads();                                        // B3

    float cp = s ? smA[s - 1] : 1.f;
    float cpc = fminf(fmaxf(cp, 1e-20f), 1.f);
    float y2 = (pv / s_psum) / cpc;

    float xs = y2;
    #pragma unroll
    for (int o = 1; o < 32; o <<= 1) {
        float y = __shfl_up_sync(0xffffffffu, xs, o);
        if (lane >= o) xs += y;
    }
    if (lane == 31) wc[wid] = xs;
    __syncthreads();                                        // B4
    if (wid == 0) {
        float a = wc[lane];
        #pragma unroll
        for (int o = 1; o < 32; o <<= 1) {
            float y = __shfl_up_sync(0xffffffffu, a, o);
            if (lane >= o) a += y;
        }
        wc[lane] = a;
    }
    __syncthreads();                                        // B5
    float cs = wid ? xs + wc[wid - 1] : xs;
    float alpha = p * cp * cs;

    float mx = c;
    #pragma unroll
    for (int j = 1; j < W_; j++) { int i = s - j; if (i >= 0) mx = fmaxf(mx, smC[i]); }
    float eu = __expf(c - mx);
    smA[s] = eu;
    __syncthreads();                                        // B6

    float den = 0.f;
    #pragma unroll
    for (int j = 0; j < W_; j++) { int i = s - j; if (i >= 0) den += smA[i]; }
    den = fmaxf(den, 1e-10f);
    float g = alpha / den;
    smC[s] = g;
    __syncthreads();                                        // B7

    float acc = 0.f;
    #pragma unroll
    for (int j = 0; j < W_; j++) { int i = s + j; if (i < S_) acc += smC[i]; }
    g_beta[base + s] = eu * acc;
}

// ---------------- K3: context = beta . value ----------------------
// Early-exit blocks whose entire beta slice is exactly 0.0f: their
// contribution is exactly zero, so skipping the value reads is
// bit-identical. Monotonic alpha underflows to 0f beyond s~250, so
// ~70% of blocks skip all DRAM traffic.
#define SCHUNK_ 32
__global__ void __launch_bounds__(256) k_ctx(const float* __restrict__ value,
                                             float* __restrict__ out) {
    int b = blockIdx.y, sc = blockIdx.x;     // 32 chunks of 32 rows
    int t = threadIdx.x;
    __shared__ float sb[SCHUNK_];
    __shared__ int s_any;
    if (t < SCHUNK_) {
        float v = g_beta[b * S_ + sc * SCHUNK_ + t];
        sb[t] = v;
        unsigned m = __ballot_sync(0xffffffffu, v != 0.f);
        if (t == 0) s_any = (m != 0u);
    }
    __syncthreads();
    if (!s_any) return;
    const float* vp = value + (((size_t)b * S_ + sc * SCHUNK_) << 9);
    float a0 = 0.f, a1 = 0.f;
    #pragma unroll
    for (int s = 0; s < SCHUNK_; s++) {
        float bs = sb[s];
        a0 += bs * vp[(s << 9) + t];
        a1 += bs * vp[(s << 9) + t + 256];
    }
    atomicAdd(out + b * 512 + t,       a0);
    atomicAdd(out + b * 512 + t + 256, a1);
}

// ---------------- launch ------------------------------------------
extern "C" void kernel_launch(void* const* d_in, const int* in_sizes, int n_in,
                              void* d_out, int out_size) {
    const float* dec   = (const float*)d_in[0];
    const float* key   = (const float*)d_in[1];
    const float* value = (const float*)d_in[2];
    const float* prev  = (const float*)d_in[3];
    const float* noise = (const float*)d_in[4];
    const float* Wm    = (const float*)d_in[5];
    const float* bm    = (const float*)d_in[6];
    const float* vm    = (const float*)d_in[7];
    const float* gm    = (const float*)d_in[8];
    const float* vbm   = (const float*)d_in[9];
    const float* rm    = (const float*)d_in[10];
    const float* Wc    = (const float*)d_in[11];
    const float* bc    = (const float*)d_in[12];
    const float* vc    = (const float*)d_in[13];
    const float* gc    = (const float*)d_in[14];
    const float* vbc   = (const float*)d_in[15];
    const float* rc    = (const float*)d_in[16];
    float* out = (float*)d_out;

    k_pre<<<dim3(32, 3), 256>>>(dec, Wm, bm, Wc, bc, vm, gm, vc, gc, out);
    k_energy<<<dim3(S_ / 32, B_), 256>>>(key, vbm, rm, vbc, rc);
    k_scan<<<B_, S_>>>(noise, prev);
    k_ctx<<<dim3(S_ / SCHUNK_, B_), 256>>>(value, out);
}